// round 12
// baseline (speedup 1.0000x reference)
#include <cuda_runtime.h>
#include <cuda_fp16.h>
#include <math.h>
#include <cstdint>

#define B 8
#define C 64
#define H 256
#define W 256
#define HW 65536
#define P 16
#define OC 64
#define NBINS 256
#define OUTC 112   // OC + (C-P)

// Device scratch
__device__ float g_act[B * C];
__device__ int   g_top[B * P];
__device__ int   g_unsel[B * (C - P)];
__device__ uint4 g_pack[B * HW * 2];   // [b][px][16ch] fp16, 32B per px (16.8MB)

__device__ __forceinline__ uint32_t smem_u32(const void* p) {
    uint32_t a;
    asm("{ .reg .u64 t; cvta.to.shared.u64 t, %1; cvt.u32.u64 %0, t; }"
        : "=r"(a) : "l"(p));
    return a;
}
__device__ __forceinline__ void cp_async16(uint32_t saddr, const void* g) {
    asm volatile("cp.async.cg.shared.global [%0], [%1], 16;"
                 :: "r"(saddr), "l"(g) : "memory");
}

// ===========================================================================
// Kernel 1: fused per-(b,c) min/max + 256-bin histogram + entropy.
// Hoisted reciprocal + Markstein correctly-rounded division (matches div.rn).
// ===========================================================================
__global__ void __launch_bounds__(512)
k_stats(const float* __restrict__ x) {
    __shared__ float smn[512], smx[512];
    __shared__ int   sh[16][NBINS];
    __shared__ float sred[512];
    __shared__ float s_mn, s_den;

    int bc  = blockIdx.x;
    int tid = threadIdx.x;
    int wid = tid >> 5;
    const float4* p = (const float4*)(x + (size_t)bc * HW);

    float mn = 3.402823466e+38f, mx = -3.402823466e+38f;
#pragma unroll 4
    for (int i = tid; i < HW / 4; i += 512) {
        float4 v = p[i];
        mn = fminf(mn, fminf(fminf(v.x, v.y), fminf(v.z, v.w)));
        mx = fmaxf(mx, fmaxf(fmaxf(v.x, v.y), fmaxf(v.z, v.w)));
    }
    smn[tid] = mn; smx[tid] = mx;
    for (int w = 0; w < 16; w++)
        if (tid < NBINS) sh[w][tid] = 0;
    __syncthreads();
    for (int s = 256; s > 0; s >>= 1) {
        if (tid < s) {
            smn[tid] = fminf(smn[tid], smn[tid + s]);
            smx[tid] = fmaxf(smx[tid], smx[tid + s]);
        }
        __syncthreads();
    }
    if (tid == 0) { s_mn = smn[0]; s_den = smx[0] - smn[0] + 1e-8f; }
    __syncthreads();

    float bmn  = s_mn, bden = s_den;
    float binv = __frcp_rn(bden);
    int* myh = sh[wid];
#pragma unroll 2
    for (int i = tid; i < HW / 4; i += 512) {
        float4 v = p[i];
        float vs[4] = {v.x, v.y, v.z, v.w};
#pragma unroll
        for (int k = 0; k < 4; k++) {
            float d  = vs[k] - bmn;
            float q0 = d * binv;
            float r  = fmaf(-bden, q0, d);
            float xn = fmaf(r, binv, q0);
            int bn = (int)(xn * 256.0f);
            bn = bn < 0 ? 0 : (bn > 255 ? 255 : bn);
            atomicAdd(&myh[bn], 1);
        }
    }
    __syncthreads();

    float hv = 0.f;
    if (tid < NBINS) {
        int cnt = 0;
#pragma unroll
        for (int w = 0; w < 16; w++) cnt += sh[w][tid];
        hv = (float)cnt + 1e-8f;
    }
    sred[tid] = hv;
    __syncthreads();
    for (int s = 256; s > 0; s >>= 1) {
        if (tid < s) sred[tid] += sred[tid + s];
        __syncthreads();
    }
    float total = sred[0];
    __syncthreads();

    float term = 0.f;
    if (tid < NBINS) {
        float prob = __fdiv_rn(hv, total);
        term = prob * logf(prob + 1e-8f);
    }
    sred[tid] = term;
    __syncthreads();
    for (int s = 256; s > 0; s >>= 1) {
        if (tid < s) sred[tid] += sred[tid + s];
        __syncthreads();
    }
    if (tid == 0) g_act[bc] = -sred[0];
}

// ===========================================================================
// Kernel 2: top-16 per batch + ascending unselected list.
// ===========================================================================
__global__ void k_topk() {
    __shared__ float sa[C];
    int b = blockIdx.x;
    if (threadIdx.x < C) sa[threadIdx.x] = g_act[b * C + threadIdx.x];
    __syncthreads();
    if (threadIdx.x != 0) return;
    bool used[C];
    for (int c = 0; c < C; c++) used[c] = false;
    for (int p = 0; p < P; p++) {
        float best = -3.402823466e+38f;
        int bi = -1;
        for (int c = 0; c < C; c++)
            if (!used[c] && sa[c] > best) { best = sa[c]; bi = c; }
        used[bi] = true;
        g_top[b * P + p] = bi;
    }
    int k = 0;
    for (int c = 0; c < C; c++)
        if (!used[c]) g_unsel[b * (C - P) + (k++)] = c;
}

// ===========================================================================
// Kernel 3: gather+pack selected channels -> g_pack[b][px][16ch] fp16.
// Coalesced per-channel reads; contiguous 32B writes per pixel.
// ===========================================================================
__global__ void __launch_bounds__(256)
k_gather(const float* __restrict__ x) {
    int blk = blockIdx.x;          // B * 128 blocks, 512 px each
    int b   = blk >> 7;
    int px0 = (blk & 127) << 9;
    int ch[16];
#pragma unroll
    for (int c = 0; c < 16; c++) ch[c] = __ldg(&g_top[b * P + c]);
    const float* xb = x + ((size_t)b * C) * HW;
#pragma unroll
    for (int u = 0; u < 2; u++) {
        int px = px0 + u * 256 + threadIdx.x;
        uint32_t q[8];
#pragma unroll
        for (int c2 = 0; c2 < 8; c2++) {
            float f0 = xb[(size_t)ch[2 * c2]     * HW + px];
            float f1 = xb[(size_t)ch[2 * c2 + 1] * HW + px];
            __half2 hp = __floats2half2_rn(f0, f1);
            q[c2] = *reinterpret_cast<uint32_t*>(&hp);
        }
        uint4* dst = g_pack + ((size_t)b * HW + px) * 2;
        dst[0] = make_uint4(q[0], q[1], q[2], q[3]);
        dst[1] = make_uint4(q[4], q[5], q[6], q[7]);
    }
}

// ===========================================================================
// Kernel 4: persistent fp16 mma conv + fused copy, double-buffered cp.async
// staging from the packed tensor (2 contiguous 16B cp.asyncs per slot).
// Tile = 2 rows x 128 px x 64 oc; K = 144 (9 taps x 16 ch), one K=16
// k-step per tap. Packed pitch 12 words (conflict-free); B pitch 72.
// ===========================================================================
#define APITCH 12
#define AROW   132
#define NSLOT  520                           // 130 x 4 active slots
#define PKD_WORDS (4 * AROW * APITCH)        // 6336 per buffer
#define BPITCH 72
#define SW_WORDS  (72 * BPITCH)              // 5184
#define CONV_SMEM ((2 * PKD_WORDS + SW_WORDS) * 4)   // 71424 bytes
#define NTILES (B * (H / 2) * (W / 128))     // 2048
#define NCTA   296
#define COPY_F4_PER_TILE 3072                // 6291456 / 2048

__global__ void __launch_bounds__(256, 2)
k_conv_mma(const float* __restrict__ x, const float* __restrict__ wgt,
           const float* __restrict__ bias, float* __restrict__ out) {
    extern __shared__ uint32_t smem_w[];
    uint32_t* pkd[2] = { smem_w, smem_w + PKD_WORDS };
    uint32_t* sW = smem_w + 2 * PKD_WORDS;
    __shared__ float sB[OC];

    int tid  = threadIdx.x;
    int wid  = tid >> 5;
    int lane = tid & 31;
    uint32_t pkdA[2] = { smem_u32(pkd[0]), smem_u32(pkd[1]) };

    // one-time: weights (half2 [72][BPITCH]) + bias
    for (int i = tid; i < 72 * OC; i += 256) {
        int oc  = i & 63;
        int row = i >> 6;
        int tap = row >> 3;
        int w2  = row & 7;
        float f0 = wgt[oc * (P * 9) + (2 * w2)     * 9 + tap];
        float f1 = wgt[oc * (P * 9) + (2 * w2 + 1) * 9 + tap];
        __half2 hp = __floats2half2_rn(f0, f1);
        sW[row * BPITCH + oc] = *reinterpret_cast<uint32_t*>(&hp);
    }
    if (tid < OC) sB[tid] = bias[tid];

    int gp = lane >> 2;
    int kc = lane & 3;
    int wrow = wid >> 2;
    int wcol = wid & 3;
    int pbase = wcol * 32 + gp;

    // stage tile into buffer bi: contiguous 32B per slot from g_pack
    auto stage_issue = [&](int tile, int bi) {
        int tb  = tile >> 8;
        int rem = tile & 255;
        int h0  = (rem >> 1) * 2;
        int w0  = (rem & 1) * 128;
        for (int i = tid; i < NSLOT; i += 256) {
            int pr = i / 130;
            int pp = i - pr * 130;
            int gw = w0 - 1 + pp;
            int gh = h0 - 1 + pr;
            uint32_t dst = pkdA[bi] + (uint32_t)((pr * AROW + pp) * APITCH) * 4u;
            if (((unsigned)gw < (unsigned)W) && ((unsigned)gh < (unsigned)H)) {
                const uint4* src = g_pack + ((size_t)tb * HW + gh * W + gw) * 2;
                cp_async16(dst,       src);
                cp_async16(dst + 16u, src + 1);
            } else {
                uint4 z = make_uint4(0u, 0u, 0u, 0u);
                *(uint4*)((char*)pkd[bi] + (dst - pkdA[bi]))      = z;
                *(uint4*)((char*)pkd[bi] + (dst - pkdA[bi]) + 16) = z;
            }
        }
        asm volatile("cp.async.commit_group;" ::: "memory");
    };

    int t0 = blockIdx.x;
    int p  = 0;
    if (t0 < NTILES) stage_issue(t0, 0);
    __syncthreads();   // weights/bias visible

    for (int t = t0; t < NTILES; t += NCTA) {
        int tn = t + NCTA;
        bool pf = (tn < NTILES);
        if (pf) stage_issue(tn, p ^ 1);
        if (pf) asm volatile("cp.async.wait_group 1;" ::: "memory");
        else    asm volatile("cp.async.wait_group 0;" ::: "memory");
        __syncthreads();

        uint32_t* sIn = pkd[p];
        int b   = t >> 8;
        int rem = t & 255;
        int h0  = (rem >> 1) * 2;
        int w0  = (rem & 1) * 128;

        float acc[2][8][4];
#pragma unroll
        for (int m = 0; m < 2; m++)
#pragma unroll
            for (int j = 0; j < 8; j++)
#pragma unroll
                for (int r = 0; r < 4; r++) acc[m][j][r] = 0.f;

#pragma unroll
        for (int tap = 0; tap < 9; tap++) {
            int arow0 = (wrow + tap / 3) * AROW + (tap % 3);
            uint32_t a[2][4];
#pragma unroll
            for (int m = 0; m < 2; m++) {
                int base0 = (arow0 + pbase + m * 16) * APITCH;
                a[m][0] = sIn[base0 + kc];
                a[m][1] = sIn[base0 + 8 * APITCH + kc];
                a[m][2] = sIn[base0 + kc + 4];
                a[m][3] = sIn[base0 + 8 * APITCH + kc + 4];
            }
            const uint32_t* b0row = sW + (tap * 8 + kc)     * BPITCH + gp;
            const uint32_t* b1row = sW + (tap * 8 + kc + 4) * BPITCH + gp;
#pragma unroll
            for (int j = 0; j < 8; j++) {
                uint32_t b0 = b0row[j * 8];
                uint32_t b1 = b1row[j * 8];
#pragma unroll
                for (int m = 0; m < 2; m++) {
                    asm volatile(
                        "mma.sync.aligned.m16n8k16.row.col.f32.f16.f16.f32 "
                        "{%0,%1,%2,%3}, {%4,%5,%6,%7}, {%8,%9}, {%0,%1,%2,%3};"
                        : "+f"(acc[m][j][0]), "+f"(acc[m][j][1]),
                          "+f"(acc[m][j][2]), "+f"(acc[m][j][3])
                        : "r"(a[m][0]), "r"(a[m][1]), "r"(a[m][2]), "r"(a[m][3]),
                          "r"(b0), "r"(b1));
                }
            }
        }

        // direct stores (8-px runs fill 32B sectors)
        size_t obase = ((size_t)b * OUTC) * HW + (size_t)(h0 + wrow) * W + w0;
#pragma unroll
        for (int m = 0; m < 2; m++) {
            int px = pbase + m * 16;
#pragma unroll
            for (int j = 0; j < 8; j++) {
                int oc0 = j * 8 + 2 * kc;
                float bb0 = sB[oc0], bb1 = sB[oc0 + 1];
                float* o0 = out + obase + (size_t)oc0 * HW + px;
                float* o1 = o0 + HW;
                o0[0] = acc[m][j][0] + bb0;
                o1[0] = acc[m][j][1] + bb1;
                o0[8] = acc[m][j][2] + bb0;
                o1[8] = acc[m][j][3] + bb1;
            }
        }

        // fused copy chunk
        {
            size_t base = (size_t)t * COPY_F4_PER_TILE;
#pragma unroll 4
            for (int i = tid; i < COPY_F4_PER_TILE; i += 256) {
                size_t tt = base + i;
                int ch_slot = (int)(tt >> 14);
                int off     = (int)(tt & 16383);
                int cb = ch_slot / (C - P);
                int j  = ch_slot - cb * (C - P);
                int cc = g_unsel[cb * (C - P) + j];
                const float4* src = (const float4*)(x + ((size_t)(cb * C + cc)) * HW);
                float4* dst = (float4*)(out + (((size_t)cb * OUTC) + OC + j) * HW);
                dst[off] = src[off];
            }
        }
        __syncthreads();   // reads of pkd[p] done before it is restaged
        p ^= 1;
    }
}

// ===========================================================================
extern "C" void kernel_launch(void* const* d_in, const int* in_sizes, int n_in,
                              void* d_out, int out_size) {
    const float* x    = (const float*)d_in[0];
    const float* wgt  = (const float*)d_in[1];
    const float* bias = (const float*)d_in[2];
    float* out = (float*)d_out;

    cudaFuncSetAttribute(k_conv_mma, cudaFuncAttributeMaxDynamicSharedMemorySize,
                         CONV_SMEM);

    k_stats<<<B * C, 512>>>(x);
    k_topk<<<B, 64>>>();
    k_gather<<<B * 128, 256>>>(x);
    k_conv_mma<<<NCTA, 256, CONV_SMEM>>>(x, wgt, bias, out);
}

// round 13
// speedup vs baseline: 1.1106x; 1.1106x over previous
#include <cuda_runtime.h>
#include <cuda_fp16.h>
#include <math.h>
#include <cstdint>

#define B 8
#define C 64
#define H 256
#define W 256
#define HW 65536
#define P 16
#define OC 64
#define NBINS 256
#define OUTC 112   // OC + (C-P)

// Device scratch
__device__ float g_act[B * C];
__device__ int   g_top[B * P];
__device__ int   g_unsel[B * (C - P)];
__device__ uint4 g_pack[B * HW * 2];   // [b][px][16ch] fp16, 32B per px

__device__ __forceinline__ uint32_t smem_u32(const void* p) {
    uint32_t a;
    asm("{ .reg .u64 t; cvta.to.shared.u64 t, %1; cvt.u32.u64 %0, t; }"
        : "=r"(a) : "l"(p));
    return a;
}
__device__ __forceinline__ void cp_async16(uint32_t saddr, const void* g) {
    asm volatile("cp.async.cg.shared.global [%0], [%1], 16;"
                 :: "r"(saddr), "l"(g) : "memory");
}

// ===========================================================================
// Kernel 1: fused per-(b,c) min/max + 256-bin histogram + entropy.
// ===========================================================================
__global__ void __launch_bounds__(512)
k_stats(const float* __restrict__ x) {
    __shared__ float smn[512], smx[512];
    __shared__ int   sh[16][NBINS];
    __shared__ float sred[512];
    __shared__ float s_mn, s_den;

    int bc  = blockIdx.x;
    int tid = threadIdx.x;
    int wid = tid >> 5;
    const float4* p = (const float4*)(x + (size_t)bc * HW);

    float mn = 3.402823466e+38f, mx = -3.402823466e+38f;
#pragma unroll 4
    for (int i = tid; i < HW / 4; i += 512) {
        float4 v = p[i];
        mn = fminf(mn, fminf(fminf(v.x, v.y), fminf(v.z, v.w)));
        mx = fmaxf(mx, fmaxf(fmaxf(v.x, v.y), fmaxf(v.z, v.w)));
    }
    smn[tid] = mn; smx[tid] = mx;
    for (int w = 0; w < 16; w++)
        if (tid < NBINS) sh[w][tid] = 0;
    __syncthreads();
    for (int s = 256; s > 0; s >>= 1) {
        if (tid < s) {
            smn[tid] = fminf(smn[tid], smn[tid + s]);
            smx[tid] = fmaxf(smx[tid], smx[tid + s]);
        }
        __syncthreads();
    }
    if (tid == 0) { s_mn = smn[0]; s_den = smx[0] - smn[0] + 1e-8f; }
    __syncthreads();

    float bmn  = s_mn, bden = s_den;
    float binv = __frcp_rn(bden);
    int* myh = sh[wid];
#pragma unroll 2
    for (int i = tid; i < HW / 4; i += 512) {
        float4 v = p[i];
        float vs[4] = {v.x, v.y, v.z, v.w};
#pragma unroll
        for (int k = 0; k < 4; k++) {
            float d  = vs[k] - bmn;
            float q0 = d * binv;                 // Markstein: matches div.rn
            float r  = fmaf(-bden, q0, d);
            float xn = fmaf(r, binv, q0);
            int bn = (int)(xn * 256.0f);
            bn = bn < 0 ? 0 : (bn > 255 ? 255 : bn);
            atomicAdd(&myh[bn], 1);
        }
    }
    __syncthreads();

    float hv = 0.f;
    if (tid < NBINS) {
        int cnt = 0;
#pragma unroll
        for (int w = 0; w < 16; w++) cnt += sh[w][tid];
        hv = (float)cnt + 1e-8f;
    }
    sred[tid] = hv;
    __syncthreads();
    for (int s = 256; s > 0; s >>= 1) {
        if (tid < s) sred[tid] += sred[tid + s];
        __syncthreads();
    }
    float total = sred[0];
    __syncthreads();

    float term = 0.f;
    if (tid < NBINS) {
        float prob = __fdiv_rn(hv, total);
        term = prob * logf(prob + 1e-8f);
    }
    sred[tid] = term;
    __syncthreads();
    for (int s = 256; s > 0; s >>= 1) {
        if (tid < s) sred[tid] += sred[tid + s];
        __syncthreads();
    }
    if (tid == 0) g_act[bc] = -sred[0];
}

// ===========================================================================
// Kernel 2: top-16 per batch + ascending unselected list.
// ===========================================================================
__global__ void k_topk() {
    __shared__ float sa[C];
    int b = blockIdx.x;
    if (threadIdx.x < C) sa[threadIdx.x] = g_act[b * C + threadIdx.x];
    __syncthreads();
    if (threadIdx.x != 0) return;
    bool used[C];
    for (int c = 0; c < C; c++) used[c] = false;
    for (int p = 0; p < P; p++) {
        float best = -3.402823466e+38f;
        int bi = -1;
        for (int c = 0; c < C; c++)
            if (!used[c] && sa[c] > best) { best = sa[c]; bi = c; }
        used[bi] = true;
        g_top[b * P + p] = bi;
    }
    int k = 0;
    for (int c = 0; c < C; c++)
        if (!used[c]) g_unsel[b * (C - P) + (k++)] = c;
}

// ===========================================================================
// Kernel 3: gather+pack selected channels -> g_pack[b][px][16ch] fp16.
// ===========================================================================
__global__ void __launch_bounds__(256)
k_gather(const float* __restrict__ x) {
    int blk = blockIdx.x;          // B * 128 blocks, 512 px each
    int b   = blk >> 7;
    int px0 = (blk & 127) << 9;
    int ch[16];
#pragma unroll
    for (int c = 0; c < 16; c++) ch[c] = __ldg(&g_top[b * P + c]);
    const float* xb = x + ((size_t)b * C) * HW;
#pragma unroll
    for (int u = 0; u < 2; u++) {
        int px = px0 + u * 256 + threadIdx.x;
        uint32_t q[8];
#pragma unroll
        for (int c2 = 0; c2 < 8; c2++) {
            float f0 = xb[(size_t)ch[2 * c2]     * HW + px];
            float f1 = xb[(size_t)ch[2 * c2 + 1] * HW + px];
            __half2 hp = __floats2half2_rn(f0, f1);
            q[c2] = *reinterpret_cast<uint32_t*>(&hp);
        }
        uint4* dst = g_pack + ((size_t)b * HW + px) * 2;
        dst[0] = make_uint4(q[0], q[1], q[2], q[3]);
        dst[1] = make_uint4(q[4], q[5], q[6], q[7]);
    }
}

// ===========================================================================
// Kernel 4: persistent fp16 mma conv + fused copy.
// Tile = 1 row x 128 px x 64 oc; 8 warps, warp = 16 px x 64 oc.
// M/N SWAP: weights are the MMA A operand (M=oc), pixels are B (N=px)
//   -> acc 32 regs/thread -> 3 CTAs/SM (24 warps), STG.64 epilogue.
// K = 144 (9 taps x 16 ch), one K=16 step per tap: 72 mma/warp/tile.
// Double-buffered cp.async staging from g_pack.
// ===========================================================================
#define APITCH 12
#define AROW   132
#define NROWS  3
#define NSLOT  (NROWS * 130)                 // 390
#define PKD_WORDS (NROWS * AROW * APITCH)    // 4752 per buffer
#define BPITCH 72
#define SW_WORDS  (72 * BPITCH)              // 5184
#define CONV_SMEM ((2 * PKD_WORDS + SW_WORDS) * 4)   // 58752 bytes
#define NTILES (B * H * (W / 128))           // 4096
#define NCTA   444
#define COPY_F4_PER_TILE 1536                // 6291456 / 4096

__global__ void __launch_bounds__(256, 3)
k_conv_mma(const float* __restrict__ x, const float* __restrict__ wgt,
           const float* __restrict__ bias, float* __restrict__ out) {
    extern __shared__ uint32_t smem_w[];
    uint32_t* pkd[2] = { smem_w, smem_w + PKD_WORDS };
    uint32_t* sW = smem_w + 2 * PKD_WORDS;
    __shared__ float sB[OC];

    int tid  = threadIdx.x;
    int wid  = tid >> 5;
    int lane = tid & 31;
    uint32_t pkdA[2] = { smem_u32(pkd[0]), smem_u32(pkd[1]) };

    // one-time: weights (half2 [tap*8+kw][BPITCH=72][oc]) + bias
    for (int i = tid; i < 72 * OC; i += 256) {
        int oc  = i & 63;
        int row = i >> 6;
        int tap = row >> 3;
        int w2  = row & 7;
        float f0 = wgt[oc * (P * 9) + (2 * w2)     * 9 + tap];
        float f1 = wgt[oc * (P * 9) + (2 * w2 + 1) * 9 + tap];
        __half2 hp = __floats2half2_rn(f0, f1);
        sW[row * BPITCH + oc] = *reinterpret_cast<uint32_t*>(&hp);
    }
    if (tid < OC) sB[tid] = bias[tid];

    int gp = lane >> 2;
    int kc = lane & 3;
    int pxchunk = wid;                 // warp owns px [wid*16, wid*16+16)

    // stage tile into buffer bi (contiguous 32B per slot from g_pack)
    auto stage_issue = [&](int tile, int bi) {
        int tb  = tile >> 9;
        int rem = tile & 511;
        int h   = rem >> 1;
        int w0  = (rem & 1) * 128;
        for (int i = tid; i < NSLOT; i += 256) {
            int pr = i / 130;
            int pp = i - pr * 130;
            int gw = w0 - 1 + pp;
            int gh = h - 1 + pr;
            uint32_t dst = pkdA[bi] + (uint32_t)((pr * AROW + pp) * APITCH) * 4u;
            if (((unsigned)gw < (unsigned)W) && ((unsigned)gh < (unsigned)H)) {
                const uint4* src = g_pack + ((size_t)tb * HW + gh * W + gw) * 2;
                cp_async16(dst,       src);
                cp_async16(dst + 16u, src + 1);
            } else {
                uint4 z = make_uint4(0u, 0u, 0u, 0u);
                *(uint4*)((char*)pkd[bi] + (dst - pkdA[bi]))      = z;
                *(uint4*)((char*)pkd[bi] + (dst - pkdA[bi]) + 16) = z;
            }
        }
        asm volatile("cp.async.commit_group;" ::: "memory");
    };

    int t0 = blockIdx.x;
    int p  = 0;
    if (t0 < NTILES) stage_issue(t0, 0);
    __syncthreads();   // weights/bias visible

    for (int t = t0; t < NTILES; t += NCTA) {
        int tn = t + NCTA;
        bool pf = (tn < NTILES);
        if (pf) stage_issue(tn, p ^ 1);
        if (pf) asm volatile("cp.async.wait_group 1;" ::: "memory");
        else    asm volatile("cp.async.wait_group 0;" ::: "memory");
        __syncthreads();

        uint32_t* sIn = pkd[p];
        int b   = t >> 9;
        int rem = t & 511;
        int h   = rem >> 1;
        int w0  = (rem & 1) * 128;

        // acc[mi][ni][4]: D[m=oc][n=px]; c0,c1 = adjacent px
        float acc[4][2][4];
#pragma unroll
        for (int mi = 0; mi < 4; mi++)
#pragma unroll
            for (int ni = 0; ni < 2; ni++)
#pragma unroll
                for (int r = 0; r < 4; r++) acc[mi][ni][r] = 0.f;

#pragma unroll
        for (int tap = 0; tap < 9; tap++) {
            int kh = tap / 3, kw = tap - kh * 3;
            // B fragments: pixels (k = channel, n = px)
            uint32_t bf[2][2];
#pragma unroll
            for (int ni = 0; ni < 2; ni++) {
                int slot = kh * AROW + pxchunk * 16 + ni * 8 + gp + kw;
                bf[ni][0] = sIn[slot * APITCH + kc];
                bf[ni][1] = sIn[slot * APITCH + kc + 4];
            }
            const uint32_t* arow0 = sW + (tap * 8 + kc)     * BPITCH;
            const uint32_t* arow1 = sW + (tap * 8 + kc + 4) * BPITCH;
#pragma unroll
            for (int mi = 0; mi < 4; mi++) {
                int oc0 = mi * 16 + gp;
                uint32_t a0 = arow0[oc0];
                uint32_t a1 = arow0[oc0 + 8];
                uint32_t a2 = arow1[oc0];
                uint32_t a3 = arow1[oc0 + 8];
#pragma unroll
                for (int ni = 0; ni < 2; ni++) {
                    asm volatile(
                        "mma.sync.aligned.m16n8k16.row.col.f32.f16.f16.f32 "
                        "{%0,%1,%2,%3}, {%4,%5,%6,%7}, {%8,%9}, {%0,%1,%2,%3};"
                        : "+f"(acc[mi][ni][0]), "+f"(acc[mi][ni][1]),
                          "+f"(acc[mi][ni][2]), "+f"(acc[mi][ni][3])
                        : "r"(a0), "r"(a1), "r"(a2), "r"(a3),
                          "r"(bf[ni][0]), "r"(bf[ni][1]));
                }
            }
        }

        // epilogue: STG.64 (adjacent px pairs), 32B runs per oc row
        size_t obase = ((size_t)b * OUTC) * HW + (size_t)h * W + w0
                     + pxchunk * 16 + 2 * kc;
#pragma unroll
        for (int mi = 0; mi < 4; mi++) {
            int oc0 = mi * 16 + gp;
            float bb0 = sB[oc0], bb8 = sB[oc0 + 8];
            float* o0 = out + obase + (size_t)oc0 * HW;
            float* o8 = o0 + (size_t)8 * HW;
#pragma unroll
            for (int ni = 0; ni < 2; ni++) {
                float2 v0 = make_float2(acc[mi][ni][0] + bb0, acc[mi][ni][1] + bb0);
                float2 v1 = make_float2(acc[mi][ni][2] + bb8, acc[mi][ni][3] + bb8);
                *(float2*)(o0 + ni * 8) = v0;
                *(float2*)(o8 + ni * 8) = v1;
            }
        }

        // fused copy chunk: 6 float4/thread, front-batched in pairs of 3
        {
            size_t base = (size_t)t * COPY_F4_PER_TILE;
#pragma unroll
            for (int it = 0; it < 2; it++) {
                float4 v[3];
                float4* dp[3];
#pragma unroll
                for (int u = 0; u < 3; u++) {
                    size_t tt = base + it * 768 + u * 256 + tid;
                    int ch_slot = (int)(tt >> 14);
                    int off     = (int)(tt & 16383);
                    int cb = ch_slot / (C - P);
                    int j  = ch_slot - cb * (C - P);
                    int cc = __ldg(&g_unsel[cb * (C - P) + j]);
                    v[u]  = ((const float4*)(x + ((size_t)(cb * C + cc)) * HW))[off];
                    dp[u] = ((float4*)(out + (((size_t)cb * OUTC) + OC + j) * HW)) + off;
                }
#pragma unroll
                for (int u = 0; u < 3; u++) *dp[u] = v[u];
            }
        }
        __syncthreads();   // reads of pkd[p] done before restage
        p ^= 1;
    }
}

// ===========================================================================
extern "C" void kernel_launch(void* const* d_in, const int* in_sizes, int n_in,
                              void* d_out, int out_size) {
    const float* x    = (const float*)d_in[0];
    const float* wgt  = (const float*)d_in[1];
    const float* bias = (const float*)d_in[2];
    float* out = (float*)d_out;

    cudaFuncSetAttribute(k_conv_mma, cudaFuncAttributeMaxDynamicSharedMemorySize,
                         CONV_SMEM);

    k_stats<<<B * C, 512>>>(x);
    k_topk<<<B, 64>>>();
    k_gather<<<B * 128, 256>>>(x);
    k_conv_mma<<<NCTA, 256, CONV_SMEM>>>(x, wgt, bias, out);
}

// round 14
// speedup vs baseline: 1.2428x; 1.1191x over previous
#include <cuda_runtime.h>
#include <cuda_fp16.h>
#include <math.h>
#include <cstdint>

#define B 8
#define C 64
#define H 256
#define W 256
#define HW 65536
#define P 16
#define OC 64
#define NBINS 256
#define OUTC 112   // OC + (C-P)

// Device scratch
__device__ float g_act[B * C];
__device__ int   g_top[B * P];
__device__ int   g_unsel[B * (C - P)];
__device__ uint4 g_pack[B * HW * 2];   // [b][px][16ch] fp16, 32B per px

__device__ __forceinline__ uint32_t smem_u32(const void* p) {
    uint32_t a;
    asm("{ .reg .u64 t; cvta.to.shared.u64 t, %1; cvt.u32.u64 %0, t; }"
        : "=r"(a) : "l"(p));
    return a;
}
__device__ __forceinline__ void cp_async16(uint32_t saddr, const void* g) {
    asm volatile("cp.async.cg.shared.global [%0], [%1], 16;"
                 :: "r"(saddr), "l"(g) : "memory");
}

// ===========================================================================
// Kernel 1: fused per-(b,c) min/max + 256-bin histogram + entropy.
// ===========================================================================
__global__ void __launch_bounds__(512)
k_stats(const float* __restrict__ x) {
    __shared__ float smn[512], smx[512];
    __shared__ int   sh[16][NBINS];
    __shared__ float sred[512];
    __shared__ float s_mn, s_den;

    int bc  = blockIdx.x;
    int tid = threadIdx.x;
    int wid = tid >> 5;
    const float4* p = (const float4*)(x + (size_t)bc * HW);

    float mn = 3.402823466e+38f, mx = -3.402823466e+38f;
#pragma unroll 4
    for (int i = tid; i < HW / 4; i += 512) {
        float4 v = p[i];
        mn = fminf(mn, fminf(fminf(v.x, v.y), fminf(v.z, v.w)));
        mx = fmaxf(mx, fmaxf(fmaxf(v.x, v.y), fmaxf(v.z, v.w)));
    }
    smn[tid] = mn; smx[tid] = mx;
    for (int w = 0; w < 16; w++)
        if (tid < NBINS) sh[w][tid] = 0;
    __syncthreads();
    for (int s = 256; s > 0; s >>= 1) {
        if (tid < s) {
            smn[tid] = fminf(smn[tid], smn[tid + s]);
            smx[tid] = fmaxf(smx[tid], smx[tid + s]);
        }
        __syncthreads();
    }
    if (tid == 0) { s_mn = smn[0]; s_den = smx[0] - smn[0] + 1e-8f; }
    __syncthreads();

    float bmn  = s_mn, bden = s_den;
    float binv = __frcp_rn(bden);
    int* myh = sh[wid];
#pragma unroll 2
    for (int i = tid; i < HW / 4; i += 512) {
        float4 v = p[i];
        float vs[4] = {v.x, v.y, v.z, v.w};
#pragma unroll
        for (int k = 0; k < 4; k++) {
            float d  = vs[k] - bmn;
            float q0 = d * binv;                 // Markstein: matches div.rn
            float r  = fmaf(-bden, q0, d);
            float xn = fmaf(r, binv, q0);
            int bn = (int)(xn * 256.0f);
            bn = bn < 0 ? 0 : (bn > 255 ? 255 : bn);
            atomicAdd(&myh[bn], 1);
        }
    }
    __syncthreads();

    float hv = 0.f;
    if (tid < NBINS) {
        int cnt = 0;
#pragma unroll
        for (int w = 0; w < 16; w++) cnt += sh[w][tid];
        hv = (float)cnt + 1e-8f;
    }
    sred[tid] = hv;
    __syncthreads();
    for (int s = 256; s > 0; s >>= 1) {
        if (tid < s) sred[tid] += sred[tid + s];
        __syncthreads();
    }
    float total = sred[0];
    __syncthreads();

    float term = 0.f;
    if (tid < NBINS) {
        float prob = __fdiv_rn(hv, total);
        term = prob * logf(prob + 1e-8f);
    }
    sred[tid] = term;
    __syncthreads();
    for (int s = 256; s > 0; s >>= 1) {
        if (tid < s) sred[tid] += sred[tid + s];
        __syncthreads();
    }
    if (tid == 0) g_act[bc] = -sred[0];
}

// ===========================================================================
// Kernel 2: top-16 per batch + ascending unselected list.
// ===========================================================================
__global__ void k_topk() {
    __shared__ float sa[C];
    int b = blockIdx.x;
    if (threadIdx.x < C) sa[threadIdx.x] = g_act[b * C + threadIdx.x];
    __syncthreads();
    if (threadIdx.x != 0) return;
    bool used[C];
    for (int c = 0; c < C; c++) used[c] = false;
    for (int p = 0; p < P; p++) {
        float best = -3.402823466e+38f;
        int bi = -1;
        for (int c = 0; c < C; c++)
            if (!used[c] && sa[c] > best) { best = sa[c]; bi = c; }
        used[bi] = true;
        g_top[b * P + p] = bi;
    }
    int k = 0;
    for (int c = 0; c < C; c++)
        if (!used[c]) g_unsel[b * (C - P) + (k++)] = c;
}

// ===========================================================================
// Kernel 3: gather+pack selected channels -> g_pack[b][px][16ch] fp16.
// ===========================================================================
__global__ void __launch_bounds__(256)
k_gather(const float* __restrict__ x) {
    int blk = blockIdx.x;          // B * 128 blocks, 512 px each
    int b   = blk >> 7;
    int px0 = (blk & 127) << 9;
    int ch[16];
#pragma unroll
    for (int c = 0; c < 16; c++) ch[c] = __ldg(&g_top[b * P + c]);
    const float* xb = x + ((size_t)b * C) * HW;
#pragma unroll
    for (int u = 0; u < 2; u++) {
        int px = px0 + u * 256 + threadIdx.x;
        uint32_t q[8];
#pragma unroll
        for (int c2 = 0; c2 < 8; c2++) {
            float f0 = xb[(size_t)ch[2 * c2]     * HW + px];
            float f1 = xb[(size_t)ch[2 * c2 + 1] * HW + px];
            __half2 hp = __floats2half2_rn(f0, f1);
            q[c2] = *reinterpret_cast<uint32_t*>(&hp);
        }
        uint4* dst = g_pack + ((size_t)b * HW + px) * 2;
        dst[0] = make_uint4(q[0], q[1], q[2], q[3]);
        dst[1] = make_uint4(q[4], q[5], q[6], q[7]);
    }
}

// ===========================================================================
// Kernel 4: persistent fp16 mma conv + fused copy, vertical ring-buffer walk.
// 16 strips (b x w-half) x 27 CTAs; each CTA walks consecutive rows h of its
// strip. Per tile only ONE new input row staged (ring of 4 row buffers).
// Warp = 16 px x 64 oc (M=oc, N=px); K = 144, one K=16 step per tap.
// Weight A-fragments pre-packed per (tap,mi,lane) as uint4 -> LDS.128.
// ===========================================================================
#define APITCH 12
#define AROW   132
#define RING_WORDS (4 * AROW * APITCH)       // 6336
#define SWF_UINT4  (9 * 4 * 32)              // 1152 fragments
#define CONV_SMEM  (RING_WORDS * 4 + SWF_UINT4 * 16)   // 25344+18432 = 43776
#define NSTRIP 16
#define CPS    27                             // CTAs per strip
#define NCTA   (NSTRIP * CPS)                 // 432
#define COPY_F4_PER_TILE 1536                 // 6291456 / 4096

__global__ void __launch_bounds__(256, 3)
k_conv_mma(const float* __restrict__ x, const float* __restrict__ wgt,
           const float* __restrict__ bias, float* __restrict__ out) {
    extern __shared__ uint32_t smem_w[];
    uint32_t* ring = smem_w;                       // 4 row buffers
    uint4*    sWf  = (uint4*)(smem_w + RING_WORDS);
    __shared__ float sB[OC];

    int tid  = threadIdx.x;
    int wid  = tid >> 5;
    int lane = tid & 31;
    uint32_t ringA = smem_u32(ring);

    // ---- one-time: pre-packed weight fragments + bias ----
    // sWf[(tap*4+mi)*32 + lane] = {a0,a1,a2,a3} for that lane's (gp,kc)
    for (int i = tid; i < SWF_UINT4; i += 256) {
        int tap = i >> 7;
        int mi  = (i >> 5) & 3;
        int ln  = i & 31;
        int gp_ = ln >> 2;
        int kc_ = ln & 3;
        int oc0 = mi * 16 + gp_;
        const float* wg = wgt;
        auto pk = [&](int oc, int k2) -> uint32_t {
            float f0 = wg[oc * (P * 9) + (2 * k2)     * 9 + tap];
            float f1 = wg[oc * (P * 9) + (2 * k2 + 1) * 9 + tap];
            __half2 hp = __floats2half2_rn(f0, f1);
            return *reinterpret_cast<uint32_t*>(&hp);
        };
        sWf[i] = make_uint4(pk(oc0, kc_), pk(oc0 + 8, kc_),
                            pk(oc0, kc_ + 4), pk(oc0 + 8, kc_ + 4));
    }
    if (tid < OC) sB[tid] = bias[tid];

    // ---- strip / row-range assignment ----
    int strip = blockIdx.x / CPS;          // 0..15
    int k     = blockIdx.x - strip * CPS;  // 0..26
    int b     = strip >> 1;
    int w0    = (strip & 1) * 128;
    int hs    = k * 9 + (k < 13 ? k : 13); // 13 CTAs get 10 rows, 14 get 9
    int cnt   = 9 + (k < 13 ? 1 : 0);
    int he    = hs + cnt;

    int gp = lane >> 2;
    int kc = lane & 3;
    int pxchunk = wid;                     // warp owns px [wid*16, +16)

    // stage one absolute input row r into ring buffer (r&3)
    auto stage_row = [&](int r) {
        int rb = (r + 4) & 3;
        uint32_t dstb = ringA + (uint32_t)(rb * AROW * APITCH) * 4u;
        if ((unsigned)r < (unsigned)H) {
            const uint4* srow = g_pack + ((size_t)b * HW + r * W) * 2;
            for (int pp = tid; pp < 130; pp += 256) {
                int gw = w0 - 1 + pp;
                uint32_t dst = dstb + (uint32_t)(pp * APITCH) * 4u;
                if ((unsigned)gw < (unsigned)W) {
                    const uint4* src = srow + gw * 2;
                    cp_async16(dst,       src);
                    cp_async16(dst + 16u, src + 1);
                } else {
                    uint4 z = make_uint4(0u, 0u, 0u, 0u);
                    *(uint4*)((char*)ring + (dst - ringA))      = z;
                    *(uint4*)((char*)ring + (dst - ringA) + 16) = z;
                }
            }
        } else {
            uint4 z = make_uint4(0u, 0u, 0u, 0u);
            for (int pp = tid; pp < 130; pp += 256) {
                uint32_t off = (uint32_t)((rb * AROW + pp) * APITCH) * 4u;
                *(uint4*)((char*)ring + off)      = z;
                *(uint4*)((char*)ring + off + 16) = z;
            }
        }
        asm volatile("cp.async.commit_group;" ::: "memory");
    };

    // prologue: stage rows hs-1, hs, hs+1 (one commit group via 3 commits;
    // count them as 3 groups)
    stage_row(hs - 1);
    stage_row(hs);
    stage_row(hs + 1);
    __syncthreads();   // sWf/sB visible; zero-fills visible

    for (int h = hs; h < he; h++) {
        bool pf = (h + 1 < he);
        if (pf) stage_row(h + 2);
        if (pf) asm volatile("cp.async.wait_group 1;" ::: "memory");
        else    asm volatile("cp.async.wait_group 0;" ::: "memory");
        __syncthreads();

        // acc[mi][ni][4]: D[m=oc][n=px]
        float acc[4][2][4];
#pragma unroll
        for (int mi = 0; mi < 4; mi++)
#pragma unroll
            for (int ni = 0; ni < 2; ni++)
#pragma unroll
                for (int r = 0; r < 4; r++) acc[mi][ni][r] = 0.f;

#pragma unroll
        for (int tap = 0; tap < 9; tap++) {
            int kh = tap / 3, kw = tap - kh * 3;
            int rb = (h - 1 + kh + 4) & 3;
            uint32_t bf[2][2];
#pragma unroll
            for (int ni = 0; ni < 2; ni++) {
                int slot = rb * AROW + pxchunk * 16 + ni * 8 + gp + kw;
                bf[ni][0] = ring[slot * APITCH + kc];
                bf[ni][1] = ring[slot * APITCH + kc + 4];
            }
#pragma unroll
            for (int mi = 0; mi < 4; mi++) {
                uint4 av = sWf[(tap * 4 + mi) * 32 + lane];   // LDS.128
#pragma unroll
                for (int ni = 0; ni < 2; ni++) {
                    asm volatile(
                        "mma.sync.aligned.m16n8k16.row.col.f32.f16.f16.f32 "
                        "{%0,%1,%2,%3}, {%4,%5,%6,%7}, {%8,%9}, {%0,%1,%2,%3};"
                        : "+f"(acc[mi][ni][0]), "+f"(acc[mi][ni][1]),
                          "+f"(acc[mi][ni][2]), "+f"(acc[mi][ni][3])
                        : "r"(av.x), "r"(av.y), "r"(av.z), "r"(av.w),
                          "r"(bf[ni][0]), "r"(bf[ni][1]));
                }
            }
        }

        // epilogue: STG.64 (adjacent px pairs)
        size_t obase = ((size_t)b * OUTC) * HW + (size_t)h * W + w0
                     + pxchunk * 16 + 2 * kc;
#pragma unroll
        for (int mi = 0; mi < 4; mi++) {
            int oc0 = mi * 16 + gp;
            float bb0 = sB[oc0], bb8 = sB[oc0 + 8];
            float* o0 = out + obase + (size_t)oc0 * HW;
            float* o8 = o0 + (size_t)8 * HW;
#pragma unroll
            for (int ni = 0; ni < 2; ni++) {
                float2 v0 = make_float2(acc[mi][ni][0] + bb0, acc[mi][ni][1] + bb0);
                float2 v1 = make_float2(acc[mi][ni][2] + bb8, acc[mi][ni][3] + bb8);
                *(float2*)(o0 + ni * 8) = v0;
                *(float2*)(o8 + ni * 8) = v1;
            }
        }

        // fused copy chunk, tile id = strip*256 + h (unique in 0..4095)
        {
            size_t base = (size_t)(strip * 256 + h) * COPY_F4_PER_TILE;
#pragma unroll
            for (int it = 0; it < 2; it++) {
                float4 v[3];
                float4* dp[3];
#pragma unroll
                for (int u = 0; u < 3; u++) {
                    size_t tt = base + it * 768 + u * 256 + tid;
                    int ch_slot = (int)(tt >> 14);
                    int off     = (int)(tt & 16383);
                    int cb = ch_slot / (C - P);
                    int j  = ch_slot - cb * (C - P);
                    int cc = __ldg(&g_unsel[cb * (C - P) + j]);
                    v[u]  = ((const float4*)(x + ((size_t)(cb * C + cc)) * HW))[off];
                    dp[u] = ((float4*)(out + (((size_t)cb * OUTC) + OC + j) * HW)) + off;
                }
#pragma unroll
                for (int u = 0; u < 3; u++) *dp[u] = v[u];
            }
        }
        __syncthreads();   // ring reads done before next-row overwrite
    }
}

// ===========================================================================
extern "C" void kernel_launch(void* const* d_in, const int* in_sizes, int n_in,
                              void* d_out, int out_size) {
    const float* x    = (const float*)d_in[0];
    const float* wgt  = (const float*)d_in[1];
    const float* bias = (const float*)d_in[2];
    float* out = (float*)d_out;

    cudaFuncSetAttribute(k_conv_mma, cudaFuncAttributeMaxDynamicSharedMemorySize,
                         CONV_SMEM);

    k_stats<<<B * C, 512>>>(x);
    k_topk<<<B, 64>>>();
    k_gather<<<B * 128, 256>>>(x);
    k_conv_mma<<<NCTA, 256, CONV_SMEM>>>(x, wgt, bias, out);
}